// round 6
// baseline (speedup 1.0000x reference)
#include <cuda_runtime.h>

// ---------------------------------------------------------------------------
// AdaptiveUnivariateFunction — fused persistent kernel (round 6).
//   xn = (x - min)/(max - min + 1e-6) in [0,1)
//   out = cp[idx] + t*(cp[idx+1]-cp[idx]),  idx=clamp(floor(xn*31),0,30)
//
// phase 1: grid-stride min/max (ascending). Early region .cs streaming;
//          last 112MB pinned with L2::evict_last (L2 = 126MB).
// barrier: arrival atomics fold (min,max) into ping-pong global slots;
//          LAST block publishes (S,B), resets alternate slot, releases.
// phase 2: each thread re-walks ITS OWN indices in REVERSE (pinned lines
//          first), .cs loads (demote-on-consume) + .cs stores.
// ---------------------------------------------------------------------------

#define NPART 1184              // 148 SMs x 8 blocks -> exactly one wave
#define NTHREADS 256
#define PIN_V4   7340032        // 112 MB / 16 B: tail float4s pinned in L2

// ping-pong (min,max) accumulators in flipped-uint space; slot = epoch & 1
__device__ unsigned int g_mm[2][2] = {{0xFFFFFFFFu, 0u}, {0xFFFFFFFFu, 0u}};
__device__ float2 g_sb[2];               // published (S, B) per slot
__device__ unsigned int g_count;         // barrier arrivals
__device__ unsigned int g_release;       // barrier epoch (monotone)

__device__ __forceinline__ unsigned int ld_acq(const unsigned int* p) {
    unsigned int v;
    asm volatile("ld.global.acquire.gpu.u32 %0, [%1];" : "=r"(v) : "l"(p));
    return v;
}
// order-preserving float<->uint (monotone under unsigned compare)
__device__ __forceinline__ unsigned int flipf(float f) {
    unsigned int u = __float_as_uint(f);
    return u ^ ((unsigned int)(-(int)(u >> 31)) | 0x80000000u);
}
__device__ __forceinline__ float unflipf(unsigned int u) {
    return __uint_as_float(u ^ (((u >> 31) - 1u) | 0x80000000u));
}
// float4 load with L2::evict_last cache-hint (pin)
__device__ __forceinline__ float4 ld_pin(const float4* p, unsigned long long pol) {
    float4 v;
    asm volatile("ld.global.L2::cache_hint.v4.f32 {%0,%1,%2,%3}, [%4], %5;"
                 : "=f"(v.x), "=f"(v.y), "=f"(v.z), "=f"(v.w)
                 : "l"(p), "l"(pol));
    return v;
}

__device__ __forceinline__ float auf_eval(float x, float S, float B,
                                          const float2* __restrict__ tab) {
    float xn31 = fmaf(x, S, B);          // xn * 31
    int idx = (int)xn31;                 // trunc == floor here
    idx = max(0, min(idx, 30));          // boundary rounding value-neutral
    float2 ad = tab[idx];                // (cp[idx], cp[idx+1]-cp[idx])
    return fmaf(xn31 - (float)idx, ad.y, ad.x);
}

__global__ void __launch_bounds__(NTHREADS, 8)
auf_fused_kernel(const float* __restrict__ xs,
                 const float* __restrict__ cp,
                 float* __restrict__ outs,
                 int n) {
    __shared__ float2 tab[32];
    __shared__ float smin[8], smax[8];
    __shared__ float s_SB[2];

    // epoch (pre-arrival read is safe: release needs THIS block's arrival)
    unsigned int epoch0 = 0;
    if (threadIdx.x == 0) epoch0 = ld_acq(&g_release);

    // spline table: (cp[i], cp[i+1]-cp[i]); slot 31 duplicates 30
    if (threadIdx.x < 32) {
        int i = (threadIdx.x < 31) ? (int)threadIdx.x : 30;
        float c0 = cp[i];
        float c1 = cp[i + 1];
        tab[threadIdx.x] = make_float2(c0, c1 - c0);
    }

    unsigned long long pol;
    asm volatile("createpolicy.fractional.L2::evict_last.b64 %0, 1.0;" : "=l"(pol));

    const float4* __restrict__ x4 = (const float4*)xs;
    const int nv4 = n >> 2;
    const int pin_start = (nv4 > PIN_V4) ? (nv4 - PIN_V4) : 0;
    const int tid0 = blockIdx.x * NTHREADS + (int)threadIdx.x;
    const int stride = NPART * NTHREADS;

    // ------------------- phase 1: min/max -------------------
    float vmin = 3.402823466e38f;
    float vmax = -3.402823466e38f;

    int i = tid0;
    #pragma unroll 4
    for (; i < pin_start; i += stride) {              // streaming region
        float4 v = __ldcs(&x4[i]);
        vmin = fminf(vmin, fminf(fminf(v.x, v.y), fminf(v.z, v.w)));
        vmax = fmaxf(vmax, fmaxf(fmaxf(v.x, v.y), fmaxf(v.z, v.w)));
    }
    #pragma unroll 4
    for (; i < nv4; i += stride) {                    // pinned tail region
        float4 v = ld_pin(&x4[i], pol);
        vmin = fminf(vmin, fminf(fminf(v.x, v.y), fminf(v.z, v.w)));
        vmax = fmaxf(vmax, fmaxf(fmaxf(v.x, v.y), fmaxf(v.z, v.w)));
    }
    if (blockIdx.x == 0 && threadIdx.x < (n & 3)) {   // scalar tail (defensive)
        float v = xs[(nv4 << 2) + threadIdx.x];
        vmin = fminf(vmin, v);
        vmax = fmaxf(vmax, v);
    }

    #pragma unroll
    for (int o = 16; o; o >>= 1) {
        vmin = fminf(vmin, __shfl_xor_sync(0xFFFFFFFFu, vmin, o));
        vmax = fmaxf(vmax, __shfl_xor_sync(0xFFFFFFFFu, vmax, o));
    }
    const int wid = threadIdx.x >> 5;
    if ((threadIdx.x & 31) == 0) { smin[wid] = vmin; smax[wid] = vmax; }
    __syncthreads();

    // ------------------- barrier with folded reduction -------------------
    if (threadIdx.x == 0) {
        float bmin = smin[0], bmax = smax[0];
        #pragma unroll
        for (int w = 1; w < 8; w++) {
            bmin = fminf(bmin, smin[w]);
            bmax = fmaxf(bmax, smax[w]);
        }
        const int s = (int)(epoch0 & 1u);
        atomicMin(&g_mm[s][0], flipf(bmin));
        atomicMax(&g_mm[s][1], flipf(bmax));
        __threadfence();
        unsigned int old = atomicAdd(&g_count, 1u);
        if (old == NPART - 1) {
            // last arrival: finalize, publish, reset other slot, release
            float fmin = unflipf(ld_acq(&g_mm[s][0]));
            float fmax = unflipf(ld_acq(&g_mm[s][1]));
            float S = 31.0f / (fmax - fmin + 1e-6f);
            g_sb[s] = make_float2(S, -fmin * S);
            g_mm[s ^ 1][0] = 0xFFFFFFFFu;            // next replay's slot
            g_mm[s ^ 1][1] = 0u;
            atomicExch(&g_count, 0u);
            __threadfence();
            atomicAdd(&g_release, 1u);
            s_SB[0] = S;
            s_SB[1] = -fmin * S;
        } else {
            while (ld_acq(&g_release) == epoch0) __nanosleep(16);
            float2 sb = g_sb[s];                     // ordered after acquire
            s_SB[0] = sb.x;
            s_SB[1] = sb.y;
        }
    }
    __syncthreads();
    const float S = s_SB[0];
    const float B = s_SB[1];

    // ------------------- phase 2: transform (own indices, reversed) -------
    // First re-reads = pinned tail (L2 hits); .cs demotes each line on its
    // single consumption, freeing pinned capacity as the sweep proceeds.
    float4* __restrict__ o4 = (float4*)outs;
    if (tid0 < nv4) {
        const int last = tid0 + ((nv4 - 1 - tid0) / stride) * stride;
        #pragma unroll 2
        for (int j = last; j >= 0; j -= stride) {
            float4 v = __ldcs(&x4[j]);
            float4 r;
            r.x = auf_eval(v.x, S, B, tab);
            r.y = auf_eval(v.y, S, B, tab);
            r.z = auf_eval(v.z, S, B, tab);
            r.w = auf_eval(v.w, S, B, tab);
            __stcs(&o4[j], r);
        }
    }
    if (blockIdx.x == 0 && threadIdx.x < (n & 3)) {   // scalar tail
        const int e = (nv4 << 2) + threadIdx.x;
        outs[e] = auf_eval(xs[e], S, B, tab);
    }
}

// ---------------------------------------------------------------------------
// Launch: ONE kernel. No sync, no allocation -> graph-capturable.
// ---------------------------------------------------------------------------
extern "C" void kernel_launch(void* const* d_in, const int* in_sizes, int n_in,
                              void* d_out, int out_size) {
    const float* x  = (const float*)d_in[0];   // (64, 1048576) fp32
    const float* cp = (const float*)d_in[1];   // (32,) control points
    // d_in[2] = knots: uniform linspace(0,1,32) -> analytic, unused
    const int n = in_sizes[0];

    auf_fused_kernel<<<NPART, NTHREADS>>>(x, cp, (float*)d_out, n);
}